// round 2
// baseline (speedup 1.0000x reference)
#include <cuda_runtime.h>
#include <math.h>

// ---------------- problem constants ----------------
#define T_TOK   65536          // B*S*H tokens
#define HD      128            // head dim
#define FF      512            // expert hidden
#define NE      8              // experts
#define MDIM    8192           // B*S
#define DDIM    1024           // model dim
#define MU      0.7f
#define GAMMA   1.0f
#define LN_EPS  1e-5f

// ---------------- scratch (device globals; no allocs allowed) ----------------
__device__ float g_t[(size_t)T_TOK * HD];          // 32 MB: t = x @ split_W + b
__device__ float g_ln[(size_t)T_TOK * HD];         // 32 MB: post-LN (merge input)
__device__ float g_pair[(size_t)2 * T_TOK * HD];   // 64 MB: per (token,expert) y+b2
__device__ int   g_gidx[2 * T_TOK];                // top-2 expert ids per token
__device__ float g_gw[2 * T_TOK];                  // top-2 gate weights per token
__device__ int   g_slot[2 * T_TOK];                // slot of each (token,k) pair
__device__ int   g_ptok[2 * T_TOK];                // slot -> token
__device__ int   g_counts[NE];
__device__ int   g_offsets[NE + 1];
__device__ int   g_cursor[NE];

// ---------------- generic fp32 SGEMM core: C = A[MxK] @ B[KxN] + bias --------
// MODE 0: A = external (x), C = g_t       (split projection)
// MODE 1: A = g_ln,         C = external  (merge projection)
template <int MODE>
__global__ __launch_bounds__(256) void sgemm_bias(
    const float* __restrict__ Aext, const float* __restrict__ B,
    const float* __restrict__ bias, float* __restrict__ Cext,
    int M, int N, int K)
{
    const float* A = (MODE == 0) ? Aext : g_ln;
    float*       C = (MODE == 0) ? g_t  : Cext;

    __shared__ __align__(16) float As[16][132];   // transposed: As[k][m]
    __shared__ __align__(16) float Bs[16][128];

    const int tid = threadIdx.x;
    const int tx = tid & 15, ty = tid >> 4;
    const int bm = blockIdx.y * 128;
    const int bn = blockIdx.x * 128;

    float acc[8][8];
#pragma unroll
    for (int i = 0; i < 8; i++)
#pragma unroll
        for (int j = 0; j < 8; j++) acc[i][j] = 0.f;

    const int ar = tid >> 2;          // 0..63
    const int ac = (tid & 3) << 2;    // 0,4,8,12
    const int br = tid >> 5;          // 0..7
    const int bc = (tid & 31) << 2;   // 0..124

    for (int k0 = 0; k0 < K; k0 += 16) {
        float4 a0 = *(const float4*)&A[(size_t)(bm + ar) * K + k0 + ac];
        float4 a1 = *(const float4*)&A[(size_t)(bm + ar + 64) * K + k0 + ac];
        As[ac + 0][ar] = a0.x; As[ac + 1][ar] = a0.y;
        As[ac + 2][ar] = a0.z; As[ac + 3][ar] = a0.w;
        As[ac + 0][ar + 64] = a1.x; As[ac + 1][ar + 64] = a1.y;
        As[ac + 2][ar + 64] = a1.z; As[ac + 3][ar + 64] = a1.w;
        *(float4*)&Bs[br][bc]     = *(const float4*)&B[(size_t)(k0 + br) * N + bn + bc];
        *(float4*)&Bs[br + 8][bc] = *(const float4*)&B[(size_t)(k0 + br + 8) * N + bn + bc];
        __syncthreads();
#pragma unroll
        for (int k = 0; k < 16; k++) {
            float a[8], b[8];
            *(float4*)&a[0] = *(const float4*)&As[k][ty * 8];
            *(float4*)&a[4] = *(const float4*)&As[k][ty * 8 + 4];
            *(float4*)&b[0] = *(const float4*)&Bs[k][tx * 8];
            *(float4*)&b[4] = *(const float4*)&Bs[k][tx * 8 + 4];
#pragma unroll
            for (int i = 0; i < 8; i++)
#pragma unroll
                for (int j = 0; j < 8; j++)
                    acc[i][j] = fmaf(a[i], b[j], acc[i][j]);
        }
        __syncthreads();
    }

    float bvs[8];
    *(float4*)&bvs[0] = *(const float4*)&bias[bn + tx * 8];
    *(float4*)&bvs[4] = *(const float4*)&bias[bn + tx * 8 + 4];
#pragma unroll
    for (int i = 0; i < 8; i++) {
        float* cp = &C[(size_t)(bm + ty * 8 + i) * N + bn + tx * 8];
        float4 o0, o1;
        o0.x = acc[i][0] + bvs[0]; o0.y = acc[i][1] + bvs[1];
        o0.z = acc[i][2] + bvs[2]; o0.w = acc[i][3] + bvs[3];
        o1.x = acc[i][4] + bvs[4]; o1.y = acc[i][5] + bvs[5];
        o1.z = acc[i][6] + bvs[6]; o1.w = acc[i][7] + bvs[7];
        *(float4*)&cp[0] = o0;
        *(float4*)&cp[4] = o1;
    }
}

// ---------------- gating: logits, top-2, softmax, per-expert counts ----------
__global__ void zero_kernel()
{
    if (threadIdx.x < NE) g_counts[threadIdx.x] = 0;
}

__global__ __launch_bounds__(256) void gate_kernel(
    const float* __restrict__ gW, const float* __restrict__ gb)
{
    __shared__ float sW[HD * NE];
    const int tid = threadIdx.x;
    for (int i = tid; i < HD * NE; i += 256) sW[i] = gW[i];
    __syncthreads();

    const int warp = tid >> 5, lane = tid & 31;
    const int tok = blockIdx.x * 8 + warp;

    float4 v = ((const float4*)(g_t + (size_t)tok * HD))[lane];
    float lg[NE];
#pragma unroll
    for (int e = 0; e < NE; e++) {
        lg[e] = v.x * sW[(lane * 4 + 0) * NE + e]
              + v.y * sW[(lane * 4 + 1) * NE + e]
              + v.z * sW[(lane * 4 + 2) * NE + e]
              + v.w * sW[(lane * 4 + 3) * NE + e];
    }
#pragma unroll
    for (int off = 16; off; off >>= 1)
#pragma unroll
        for (int e = 0; e < NE; e++)
            lg[e] += __shfl_xor_sync(0xFFFFFFFFu, lg[e], off);

    if (lane == 0) {
#pragma unroll
        for (int e = 0; e < NE; e++) lg[e] += gb[e];
        // top-1 (earliest index on ties, matching lax.top_k)
        int i0 = 0; float v0 = lg[0];
#pragma unroll
        for (int e = 1; e < NE; e++) if (lg[e] > v0) { v0 = lg[e]; i0 = e; }
        // top-2 among the rest
        int i1 = -1; float v1 = -INFINITY;
#pragma unroll
        for (int e = 0; e < NE; e++)
            if (e != i0 && lg[e] > v1) { v1 = lg[e]; i1 = e; }
        float e1 = expf(v1 - v0);
        float inv = 1.f / (1.f + e1);
        g_gidx[2 * tok]     = i0;  g_gw[2 * tok]     = inv;
        g_gidx[2 * tok + 1] = i1;  g_gw[2 * tok + 1] = e1 * inv;
        atomicAdd(&g_counts[i0], 1);
        atomicAdd(&g_counts[i1], 1);
    }
}

__global__ void scan_kernel()
{
    if (threadIdx.x == 0) {
        int o = 0;
        g_offsets[0] = 0;
        for (int e = 0; e < NE; e++) { o += g_counts[e]; g_offsets[e + 1] = o; }
        for (int e = 0; e < NE; e++) g_cursor[e] = g_offsets[e];
    }
}

__global__ __launch_bounds__(256) void scatter_kernel()
{
    int tok = blockIdx.x * 256 + threadIdx.x;
    if (tok >= T_TOK) return;
#pragma unroll
    for (int k = 0; k < 2; k++) {
        int e = g_gidx[2 * tok + k];
        int s = atomicAdd(&g_cursor[e], 1);
        g_slot[2 * tok + k] = s;
        g_ptok[s] = tok;
    }
}

// ---------------- fused expert FFN: 32 tokens/block, one expert --------------
__global__ __launch_bounds__(256) void expert_kernel(
    const float* __restrict__ W1, const float* __restrict__ b1,
    const float* __restrict__ W2, const float* __restrict__ b2)
{
    const int e = blockIdx.y;
    const int off = g_offsets[e];
    const int n = g_offsets[e + 1] - off;
    const int base = blockIdx.x * 32;
    if (base >= n) return;

    __shared__ __align__(16) float Ts[32][HD];
    __shared__ __align__(16) float Hs[32][128];
    __shared__ int stok[32];

    const int tid = threadIdx.x;
    if (tid < 32) {
        int r = base + tid;
        stok[tid] = g_ptok[off + (r < n ? r : n - 1)];
    }
    __syncthreads();
    for (int i = tid; i < 32 * 32; i += 256) {
        int row = i >> 5, q = i & 31;
        ((float4*)Ts[row])[q] = ((const float4*)(g_t + (size_t)stok[row] * HD))[q];
    }
    __syncthreads();

    const int ty = tid >> 5, tx = tid & 31;
    const float* W1e = W1 + (size_t)e * HD * FF;
    const float* W2e = W2 + (size_t)e * FF * HD;
    const float* b1e = b1 + e * FF;

    float acc[4][4];
#pragma unroll
    for (int r = 0; r < 4; r++)
#pragma unroll
        for (int c = 0; c < 4; c++) acc[r][c] = 0.f;

    for (int kc = 0; kc < 4; kc++) {
        float a1[4][4];
#pragma unroll
        for (int r = 0; r < 4; r++)
#pragma unroll
            for (int c = 0; c < 4; c++) a1[r][c] = 0.f;

#pragma unroll 4
        for (int d = 0; d < HD; d++) {
            float t0 = Ts[ty * 4 + 0][d];
            float t1 = Ts[ty * 4 + 1][d];
            float t2 = Ts[ty * 4 + 2][d];
            float t3 = Ts[ty * 4 + 3][d];
            const float* wrow = W1e + (size_t)d * FF + kc * 128 + tx;
#pragma unroll
            for (int c = 0; c < 4; c++) {
                float w = wrow[c * 32];
                a1[0][c] = fmaf(t0, w, a1[0][c]);
                a1[1][c] = fmaf(t1, w, a1[1][c]);
                a1[2][c] = fmaf(t2, w, a1[2][c]);
                a1[3][c] = fmaf(t3, w, a1[3][c]);
            }
        }
#pragma unroll
        for (int c = 0; c < 4; c++) {
            float bb = b1e[kc * 128 + c * 32 + tx];
#pragma unroll
            for (int r = 0; r < 4; r++)
                Hs[ty * 4 + r][c * 32 + tx] = fmaxf(a1[r][c] + bb, 0.f);
        }
        __syncwarp();   // Hs rows are warp-private; cross-lane only

#pragma unroll 4
        for (int k = 0; k < 128; k++) {
            float h0 = Hs[ty * 4 + 0][k];
            float h1 = Hs[ty * 4 + 1][k];
            float h2 = Hs[ty * 4 + 2][k];
            float h3 = Hs[ty * 4 + 3][k];
            const float* wrow = W2e + (size_t)(kc * 128 + k) * HD + tx;
#pragma unroll
            for (int c = 0; c < 4; c++) {
                float w = wrow[c * 32];
                acc[0][c] = fmaf(h0, w, acc[0][c]);
                acc[1][c] = fmaf(h1, w, acc[1][c]);
                acc[2][c] = fmaf(h2, w, acc[2][c]);
                acc[3][c] = fmaf(h3, w, acc[3][c]);
            }
        }
        __syncwarp();
    }

    const float* b2e = b2 + e * HD;
#pragma unroll
    for (int r = 0; r < 4; r++) {
        int rr = base + ty * 4 + r;
        if (rr < n) {
            float* outp = g_pair + (size_t)(off + rr) * HD;
#pragma unroll
            for (int c = 0; c < 4; c++)
                outp[c * 32 + tx] = acc[r][c] + b2e[c * 32 + tx];
        }
    }
}

// ---------------- combine: new_momentum = mu*m - (g0*y0 + g1*y1) -------------
__global__ __launch_bounds__(256) void combine_kernel(
    const float* __restrict__ mom_in, float* __restrict__ mom_out)
{
    int i = blockIdx.x * 256 + threadIdx.x;   // float4 index
    int tok = i >> 5, q = i & 31;
    int s0 = g_slot[2 * tok], s1 = g_slot[2 * tok + 1];
    float g0 = g_gw[2 * tok], g1 = g_gw[2 * tok + 1];
    float4 m  = ((const float4*)mom_in)[i];
    float4 y0 = ((const float4*)g_pair)[(size_t)s0 * 32 + q];
    float4 y1 = ((const float4*)g_pair)[(size_t)s1 * 32 + q];
    float4 o;
    o.x = MU * m.x - (g0 * y0.x + g1 * y1.x);
    o.y = MU * m.y - (g0 * y0.y + g1 * y1.y);
    o.z = MU * m.z - (g0 * y0.z + g1 * y1.z);
    o.w = MU * m.w - (g0 * y0.w + g1 * y1.w);
    ((float4*)mom_out)[i] = o;
}

// ---------------- layernorm over head dim ------------------------------------
__global__ __launch_bounds__(256) void ln_kernel(
    const float* __restrict__ mom, const float* __restrict__ lng,
    const float* __restrict__ lnb)
{
    const int warp = threadIdx.x >> 5, lane = threadIdx.x & 31;
    const int tok = blockIdx.x * 8 + warp;

    float4 a = ((const float4*)(g_t + (size_t)tok * HD))[lane];
    float4 b = ((const float4*)(mom + (size_t)tok * HD))[lane];
    float4 x;
    x.x = a.x + GAMMA * b.x; x.y = a.y + GAMMA * b.y;
    x.z = a.z + GAMMA * b.z; x.w = a.w + GAMMA * b.w;

    float s = x.x + x.y + x.z + x.w;
#pragma unroll
    for (int o = 16; o; o >>= 1) s += __shfl_xor_sync(0xFFFFFFFFu, s, o);
    float mean = s * (1.f / 128.f);

    float dx = x.x - mean, dy = x.y - mean, dz = x.z - mean, dw = x.w - mean;
    float sq = dx * dx + dy * dy + dz * dz + dw * dw;
#pragma unroll
    for (int o = 16; o; o >>= 1) sq += __shfl_xor_sync(0xFFFFFFFFu, sq, o);
    float rstd = rsqrtf(sq * (1.f / 128.f) + LN_EPS);

    float4 g = ((const float4*)lng)[lane];
    float4 bb = ((const float4*)lnb)[lane];
    float4 o4;
    o4.x = dx * rstd * g.x + bb.x;
    o4.y = dy * rstd * g.y + bb.y;
    o4.z = dz * rstd * g.z + bb.z;
    o4.w = dw * rstd * g.w + bb.w;
    ((float4*)(g_ln + (size_t)tok * HD))[lane] = o4;
}

// ---------------- launch ------------------------------------------------------
extern "C" void kernel_launch(void* const* d_in, const int* in_sizes, int n_in,
                              void* d_out, int out_size)
{
    const float* x        = (const float*)d_in[0];
    const float* momentum = (const float*)d_in[1];
    const float* split_W  = (const float*)d_in[2];
    const float* split_b  = (const float*)d_in[3];
    const float* gate_W   = (const float*)d_in[4];
    const float* gate_b   = (const float*)d_in[5];
    const float* W1       = (const float*)d_in[6];
    const float* b1       = (const float*)d_in[7];
    const float* W2       = (const float*)d_in[8];
    const float* b2       = (const float*)d_in[9];
    const float* ln_g     = (const float*)d_in[10];
    const float* ln_b     = (const float*)d_in[11];
    const float* merge_W  = (const float*)d_in[12];
    const float* merge_b  = (const float*)d_in[13];

    float* out_final = (float*)d_out;
    float* out_mom   = out_final + (size_t)MDIM * DDIM;

    dim3 gemm_grid(DDIM / 128, MDIM / 128);

    sgemm_bias<0><<<gemm_grid, 256>>>(x, split_W, split_b, nullptr, MDIM, DDIM, DDIM);
    zero_kernel<<<1, 32>>>();
    gate_kernel<<<T_TOK / 8, 256>>>(gate_W, gate_b);
    scan_kernel<<<1, 1>>>();
    scatter_kernel<<<T_TOK / 256, 256>>>();
    expert_kernel<<<dim3(T_TOK / 32, NE), 256>>>(W1, b1, W2, b2);
    combine_kernel<<<(T_TOK * (HD / 4)) / 256, 256>>>(momentum, out_mom);
    ln_kernel<<<T_TOK / 8, 256>>>(out_mom, ln_g, ln_b);
    sgemm_bias<1><<<gemm_grid, 256>>>(nullptr, merge_W, merge_b, out_final, MDIM, DDIM, DDIM);
}

// round 4
// speedup vs baseline: 1.0559x; 1.0559x over previous
#include <cuda_runtime.h>
#include <math.h>

// ---------------- problem constants ----------------
#define T_TOK   65536          // B*S*H tokens
#define HD      128            // head dim
#define FF      512            // expert hidden
#define NE      8              // experts
#define MDIM    8192           // B*S
#define DDIM    1024           // model dim
#define MU      0.7f
#define GAMMA   1.0f
#define LN_EPS  1e-5f

// ---------------- scratch (device globals; no allocs allowed) ----------------
__device__ float g_t[(size_t)T_TOK * HD];          // 32 MB: t = x @ split_W + b
__device__ float g_ln[(size_t)T_TOK * HD];         // 32 MB: post-LN (merge input)
__device__ float g_pair[(size_t)2 * T_TOK * HD];   // 64 MB: per (token,expert) y+b2
__device__ int   g_gidx[2 * T_TOK];
__device__ float g_gw[2 * T_TOK];
__device__ int   g_slot[2 * T_TOK];
__device__ int   g_ptok[2 * T_TOK];
__device__ int   g_counts[NE];
__device__ int   g_offsets[NE + 1];
__device__ int   g_cursor[NE];

// ---------------- ptx helpers ----------------
__device__ __forceinline__ void cp_async16(void* smem_dst, const void* gsrc) {
    unsigned s = (unsigned)__cvta_generic_to_shared(smem_dst);
    asm volatile("cp.async.cg.shared.global [%0], [%1], 16;\n" :: "r"(s), "l"(gsrc));
}
__device__ __forceinline__ unsigned f2tf32(float f) {
    unsigned u;
    asm("cvt.rna.tf32.f32 %0, %1;" : "=r"(u) : "f"(f));
    return u;
}
// split into hi (tf32) and lo (tf32 of residual)
__device__ __forceinline__ void tf32_split(float x, unsigned& hi, unsigned& lo) {
    hi = f2tf32(x);
    lo = f2tf32(x - __uint_as_float(hi));
}
__device__ __forceinline__ void mma_tf32(float* d, const unsigned* a, const unsigned* b) {
    asm volatile(
        "mma.sync.aligned.m16n8k8.row.col.f32.tf32.tf32.f32 "
        "{%0,%1,%2,%3}, {%4,%5,%6,%7}, {%8,%9}, {%0,%1,%2,%3};\n"
        : "+f"(d[0]), "+f"(d[1]), "+f"(d[2]), "+f"(d[3])
        : "r"(a[0]), "r"(a[1]), "r"(a[2]), "r"(a[3]), "r"(b[0]), "r"(b[1]));
}

// ---------------- 3xTF32 tensor-core GEMM: C = A[MxK] @ B[KxN] + bias --------
// MODE 0: A = external (x), C = g_t       (split projection)
// MODE 1: A = g_ln,         C = external  (merge projection)
// Block tile 128x128, K-tile 16, 256 threads = 8 warps (2 M x 4 N), warp 64x32.
// Each product computed as a_hi*b_hi + a_hi*b_lo + a_lo*b_hi (near-fp32 accuracy).
template <int MODE>
__global__ __launch_bounds__(256) void tgemm_bias(
    const float* __restrict__ Aext, const float* __restrict__ B,
    const float* __restrict__ bias, float* __restrict__ Cext,
    int M, int N, int K)
{
    const float* A = (MODE == 0) ? Aext : g_ln;
    float*       C = (MODE == 0) ? g_t  : Cext;

    __shared__ __align__(16) float As[2][128][20];   // [m][k], pad 20
    __shared__ __align__(16) float Bs[2][16][136];   // [k][n], pad 136

    const int tid  = threadIdx.x;
    const int lane = tid & 31;
    const int warp = tid >> 5;
    const int wm = warp >> 2;          // 0..1
    const int wn = warp & 3;           // 0..3
    const int bm = blockIdx.y * 128;
    const int bn = blockIdx.x * 128;

    float acc[4][4][4];
#pragma unroll
    for (int mt = 0; mt < 4; mt++)
#pragma unroll
        for (int nt = 0; nt < 4; nt++)
#pragma unroll
            for (int r = 0; r < 4; r++) acc[mt][nt][r] = 0.f;

    const int nkt = K / 16;

    auto load_tile = [&](int kt, int s) {
        const float* Ab = A + (size_t)bm * K + kt * 16;
#pragma unroll
        for (int i = 0; i < 2; i++) {
            int id = tid + 256 * i;
            int row = id >> 2, c4 = id & 3;
            cp_async16(&As[s][row][c4 * 4], Ab + (size_t)row * K + c4 * 4);
        }
        const float* Bb = B + (size_t)(kt * 16) * N + bn;
#pragma unroll
        for (int i = 0; i < 2; i++) {
            int id = tid + 256 * i;
            int row = id >> 5, c4 = id & 31;
            cp_async16(&Bs[s][row][c4 * 4], Bb + (size_t)row * N + c4 * 4);
        }
        asm volatile("cp.async.commit_group;\n");
    };

    load_tile(0, 0);

    const int arow = wm * 64 + (lane >> 2);
    const int acol = lane & 3;
    const int bcol = wn * 32 + (lane >> 2);
    const int bkr  = lane & 3;

    for (int kt = 0; kt < nkt; kt++) {
        int s = kt & 1;
        if (kt + 1 < nkt) {
            load_tile(kt + 1, s ^ 1);
            asm volatile("cp.async.wait_group 1;\n");
        } else {
            asm volatile("cp.async.wait_group 0;\n");
        }
        __syncthreads();

#pragma unroll
        for (int ks = 0; ks < 2; ks++) {
            unsigned ah[4][4], al[4][4];
#pragma unroll
            for (int mt = 0; mt < 4; mt++) {
                int r0 = arow + mt * 16;
                int c0 = ks * 8 + acol;
                tf32_split(As[s][r0    ][c0    ], ah[mt][0], al[mt][0]);
                tf32_split(As[s][r0 + 8][c0    ], ah[mt][1], al[mt][1]);
                tf32_split(As[s][r0    ][c0 + 4], ah[mt][2], al[mt][2]);
                tf32_split(As[s][r0 + 8][c0 + 4], ah[mt][3], al[mt][3]);
            }
            unsigned bh[4][2], bl[4][2];
#pragma unroll
            for (int nt = 0; nt < 4; nt++) {
                int k0 = ks * 8 + bkr;
                int n0 = bcol + nt * 8;
                tf32_split(Bs[s][k0    ][n0], bh[nt][0], bl[nt][0]);
                tf32_split(Bs[s][k0 + 4][n0], bh[nt][1], bl[nt][1]);
            }
#pragma unroll
            for (int mt = 0; mt < 4; mt++)
#pragma unroll
                for (int nt = 0; nt < 4; nt++) {
                    mma_tf32(acc[mt][nt], al[mt], bh[nt]);  // a_lo * b_hi
                    mma_tf32(acc[mt][nt], ah[mt], bl[nt]);  // a_hi * b_lo
                    mma_tf32(acc[mt][nt], ah[mt], bh[nt]);  // a_hi * b_hi
                }
        }
        __syncthreads();
    }

    // epilogue: D layout c0,c1 at (row=lane>>2, col=2*(lane&3)), c2,c3 at row+8
#pragma unroll
    for (int mt = 0; mt < 4; mt++) {
#pragma unroll
        for (int nt = 0; nt < 4; nt++) {
            int m0 = bm + wm * 64 + mt * 16 + (lane >> 2);
            int n0 = bn + wn * 32 + nt * 8 + 2 * (lane & 3);
            float b0 = bias[n0], b1 = bias[n0 + 1];
            float2 v0 = make_float2(acc[mt][nt][0] + b0, acc[mt][nt][1] + b1);
            float2 v1 = make_float2(acc[mt][nt][2] + b0, acc[mt][nt][3] + b1);
            *(float2*)&C[(size_t)m0 * N + n0]       = v0;
            *(float2*)&C[(size_t)(m0 + 8) * N + n0] = v1;
        }
    }
}

// ---------------- gating: logits, top-2, softmax, per-expert counts ----------
__global__ void zero_kernel()
{
    if (threadIdx.x < NE) g_counts[threadIdx.x] = 0;
}

__global__ __launch_bounds__(256) void gate_kernel(
    const float* __restrict__ gW, const float* __restrict__ gb)
{
    __shared__ float sW[HD * NE];
    const int tid = threadIdx.x;
    for (int i = tid; i < HD * NE; i += 256) sW[i] = gW[i];
    __syncthreads();

    const int warp = tid >> 5, lane = tid & 31;
    const int tok = blockIdx.x * 8 + warp;

    float4 v = ((const float4*)(g_t + (size_t)tok * HD))[lane];
    float lg[NE];
#pragma unroll
    for (int e = 0; e < NE; e++) {
        lg[e] = v.x * sW[(lane * 4 + 0) * NE + e]
              + v.y * sW[(lane * 4 + 1) * NE + e]
              + v.z * sW[(lane * 4 + 2) * NE + e]
              + v.w * sW[(lane * 4 + 3) * NE + e];
    }
#pragma unroll
    for (int off = 16; off; off >>= 1)
#pragma unroll
        for (int e = 0; e < NE; e++)
            lg[e] += __shfl_xor_sync(0xFFFFFFFFu, lg[e], off);

    if (lane == 0) {
#pragma unroll
        for (int e = 0; e < NE; e++) lg[e] += gb[e];
        int i0 = 0; float v0 = lg[0];
#pragma unroll
        for (int e = 1; e < NE; e++) if (lg[e] > v0) { v0 = lg[e]; i0 = e; }
        int i1 = -1; float v1 = -INFINITY;
#pragma unroll
        for (int e = 0; e < NE; e++)
            if (e != i0 && lg[e] > v1) { v1 = lg[e]; i1 = e; }
        float e1 = expf(v1 - v0);
        float inv = 1.f / (1.f + e1);
        g_gidx[2 * tok]     = i0;  g_gw[2 * tok]     = inv;
        g_gidx[2 * tok + 1] = i1;  g_gw[2 * tok + 1] = e1 * inv;
        atomicAdd(&g_counts[i0], 1);
        atomicAdd(&g_counts[i1], 1);
    }
}

__global__ void scan_kernel()
{
    if (threadIdx.x == 0) {
        int o = 0;
        g_offsets[0] = 0;
        for (int e = 0; e < NE; e++) { o += g_counts[e]; g_offsets[e + 1] = o; }
        for (int e = 0; e < NE; e++) g_cursor[e] = g_offsets[e];
    }
}

__global__ __launch_bounds__(256) void scatter_kernel()
{
    int tok = blockIdx.x * 256 + threadIdx.x;
    if (tok >= T_TOK) return;
#pragma unroll
    for (int k = 0; k < 2; k++) {
        int e = g_gidx[2 * tok + k];
        int s = atomicAdd(&g_cursor[e], 1);
        g_slot[2 * tok + k] = s;
        g_ptok[s] = tok;
    }
}

// ---------------- fused expert FFN: 32 tokens/block, one expert --------------
__global__ __launch_bounds__(256) void expert_kernel(
    const float* __restrict__ W1, const float* __restrict__ b1,
    const float* __restrict__ W2, const float* __restrict__ b2)
{
    const int e = blockIdx.y;
    const int off = g_offsets[e];
    const int n = g_offsets[e + 1] - off;
    const int base = blockIdx.x * 32;
    if (base >= n) return;

    __shared__ __align__(16) float Ts[32][HD];
    __shared__ __align__(16) float Hs[32][128];
    __shared__ int stok[32];

    const int tid = threadIdx.x;
    if (tid < 32) {
        int r = base + tid;
        stok[tid] = g_ptok[off + (r < n ? r : n - 1)];
    }
    __syncthreads();
    for (int i = tid; i < 32 * 32; i += 256) {
        int row = i >> 5, q = i & 31;
        ((float4*)Ts[row])[q] = ((const float4*)(g_t + (size_t)stok[row] * HD))[q];
    }
    __syncthreads();

    const int ty = tid >> 5, tx = tid & 31;
    const float* W1e = W1 + (size_t)e * HD * FF;
    const float* W2e = W2 + (size_t)e * FF * HD;
    const float* b1e = b1 + e * FF;

    float acc[4][4];
#pragma unroll
    for (int r = 0; r < 4; r++)
#pragma unroll
        for (int c = 0; c < 4; c++) acc[r][c] = 0.f;

    for (int kc = 0; kc < 4; kc++) {
        float a1[4][4];
#pragma unroll
        for (int r = 0; r < 4; r++)
#pragma unroll
            for (int c = 0; c < 4; c++) a1[r][c] = 0.f;

#pragma unroll 4
        for (int d = 0; d < HD; d++) {
            float t0 = Ts[ty * 4 + 0][d];
            float t1 = Ts[ty * 4 + 1][d];
            float t2 = Ts[ty * 4 + 2][d];
            float t3 = Ts[ty * 4 + 3][d];
            const float* wrow = W1e + (size_t)d * FF + kc * 128 + tx;
#pragma unroll
            for (int c = 0; c < 4; c++) {
                float w = wrow[c * 32];
                a1[0][c] = fmaf(t0, w, a1[0][c]);
                a1[1][c] = fmaf(t1, w, a1[1][c]);
                a1[2][c] = fmaf(t2, w, a1[2][c]);
                a1[3][c] = fmaf(t3, w, a1[3][c]);
            }
        }
#pragma unroll
        for (int c = 0; c < 4; c++) {
            float bb = b1e[kc * 128 + c * 32 + tx];
#pragma unroll
            for (int r = 0; r < 4; r++)
                Hs[ty * 4 + r][c * 32 + tx] = fmaxf(a1[r][c] + bb, 0.f);
        }
        __syncwarp();

#pragma unroll 4
        for (int k = 0; k < 128; k++) {
            float h0 = Hs[ty * 4 + 0][k];
            float h1 = Hs[ty * 4 + 1][k];
            float h2 = Hs[ty * 4 + 2][k];
            float h3 = Hs[ty * 4 + 3][k];
            const float* wrow = W2e + (size_t)(kc * 128 + k) * HD + tx;
#pragma unroll
            for (int c = 0; c < 4; c++) {
                float w = wrow[c * 32];
                acc[0][c] = fmaf(h0, w, acc[0][c]);
                acc[1][c] = fmaf(h1, w, acc[1][c]);
                acc[2][c] = fmaf(h2, w, acc[2][c]);
                acc[3][c] = fmaf(h3, w, acc[3][c]);
            }
        }
        __syncwarp();
    }

    const float* b2e = b2 + e * HD;
#pragma unroll
    for (int r = 0; r < 4; r++) {
        int rr = base + ty * 4 + r;
        if (rr < n) {
            float* outp = g_pair + (size_t)(off + rr) * HD;
#pragma unroll
            for (int c = 0; c < 4; c++)
                outp[c * 32 + tx] = acc[r][c] + b2e[c * 32 + tx];
        }
    }
}

// ---------------- combine: new_momentum = mu*m - (g0*y0 + g1*y1) -------------
__global__ __launch_bounds__(256) void combine_kernel(
    const float* __restrict__ mom_in, float* __restrict__ mom_out)
{
    int i = blockIdx.x * 256 + threadIdx.x;   // float4 index
    int tok = i >> 5, q = i & 31;
    int s0 = g_slot[2 * tok], s1 = g_slot[2 * tok + 1];
    float g0 = g_gw[2 * tok], g1 = g_gw[2 * tok + 1];
    float4 m  = ((const float4*)mom_in)[i];
    float4 y0 = ((const float4*)g_pair)[(size_t)s0 * 32 + q];
    float4 y1 = ((const float4*)g_pair)[(size_t)s1 * 32 + q];
    float4 o;
    o.x = MU * m.x - (g0 * y0.x + g1 * y1.x);
    o.y = MU * m.y - (g0 * y0.y + g1 * y1.y);
    o.z = MU * m.z - (g0 * y0.z + g1 * y1.z);
    o.w = MU * m.w - (g0 * y0.w + g1 * y1.w);
    ((float4*)mom_out)[i] = o;
}

// ---------------- layernorm over head dim ------------------------------------
__global__ __launch_bounds__(256) void ln_kernel(
    const float* __restrict__ mom, const float* __restrict__ lng,
    const float* __restrict__ lnb)
{
    const int warp = threadIdx.x >> 5, lane = threadIdx.x & 31;
    const int tok = blockIdx.x * 8 + warp;

    float4 a = ((const float4*)(g_t + (size_t)tok * HD))[lane];
    float4 b = ((const float4*)(mom + (size_t)tok * HD))[lane];
    float4 x;
    x.x = a.x + GAMMA * b.x; x.y = a.y + GAMMA * b.y;
    x.z = a.z + GAMMA * b.z; x.w = a.w + GAMMA * b.w;

    float s = x.x + x.y + x.z + x.w;
#pragma unroll
    for (int o = 16; o; o >>= 1) s += __shfl_xor_sync(0xFFFFFFFFu, s, o);
    float mean = s * (1.f / 128.f);

    float dx = x.x - mean, dy = x.y - mean, dz = x.z - mean, dw = x.w - mean;
    float sq = dx * dx + dy * dy + dz * dz + dw * dw;
#pragma unroll
    for (int o = 16; o; o >>= 1) sq += __shfl_xor_sync(0xFFFFFFFFu, sq, o);
    float rstd = rsqrtf(sq * (1.f / 128.f) + LN_EPS);

    float4 g = ((const float4*)lng)[lane];
    float4 bb = ((const float4*)lnb)[lane];
    float4 o4;
    o4.x = dx * rstd * g.x + bb.x;
    o4.y = dy * rstd * g.y + bb.y;
    o4.z = dz * rstd * g.z + bb.z;
    o4.w = dw * rstd * g.w + bb.w;
    ((float4*)(g_ln + (size_t)tok * HD))[lane] = o4;
}

// ---------------- launch ------------------------------------------------------
extern "C" void kernel_launch(void* const* d_in, const int* in_sizes, int n_in,
                              void* d_out, int out_size)
{
    const float* x        = (const float*)d_in[0];
    const float* momentum = (const float*)d_in[1];
    const float* split_W  = (const float*)d_in[2];
    const float* split_b  = (const float*)d_in[3];
    const float* gate_W   = (const float*)d_in[4];
    const float* gate_b   = (const float*)d_in[5];
    const float* W1       = (const float*)d_in[6];
    const float* b1       = (const float*)d_in[7];
    const float* W2       = (const float*)d_in[8];
    const float* b2       = (const float*)d_in[9];
    const float* ln_g     = (const float*)d_in[10];
    const float* ln_b     = (const float*)d_in[11];
    const float* merge_W  = (const float*)d_in[12];
    const float* merge_b  = (const float*)d_in[13];

    float* out_final = (float*)d_out;
    float* out_mom   = out_final + (size_t)MDIM * DDIM;

    dim3 gemm_grid(DDIM / 128, MDIM / 128);

    tgemm_bias<0><<<gemm_grid, 256>>>(x, split_W, split_b, nullptr, MDIM, DDIM, DDIM);
    zero_kernel<<<1, 32>>>();
    gate_kernel<<<T_TOK / 8, 256>>>(gate_W, gate_b);
    scan_kernel<<<1, 1>>>();
    scatter_kernel<<<T_TOK / 256, 256>>>();
    expert_kernel<<<dim3(T_TOK / 32, NE), 256>>>(W1, b1, W2, b2);
    combine_kernel<<<(T_TOK * (HD / 4)) / 256, 256>>>(momentum, out_mom);
    ln_kernel<<<T_TOK / 8, 256>>>(out_mom, ln_g, ln_b);
    tgemm_bias<1><<<gemm_grid, 256>>>(nullptr, merge_W, merge_b, out_final, MDIM, DDIM, DDIM);
}